// round 9
// baseline (speedup 1.0000x reference)
#include <cuda_runtime.h>
#include <cstdint>

#define NU 50000
#define NI 50000
#define FH 128
#define EC 800000
#define GC 512
#define CC 16
#define LC 3
#define BN_EPS 1e-5f
#define DEGCAP 96
#define NT 391

#define NODEF (50000ull * 128ull)
#define OFF_XU 0ull
#define OFF_XI (1ull * NODEF)
#define OFF_AGU (2ull * NODEF)
#define OFF_AGI (3ull * NODEF)
#define OFF_NWU (4ull * NODEF)
#define OFF_NWI (5ull * NODEF)
#define OFF_CNT (6ull * NODEF)
#define OFF_INV (OFF_CNT + 512ull)
#define OFF_STATS (OFF_INV + 512ull)
#define OFF_BN (OFF_STATS + 512ull)
#define BUF_TOTAL (OFF_BN + 512ull)

__device__ float g_buf[BUF_TOTAL];
__device__ int g_deg[2 * 50000];
__device__ int g_csr[2ull * 50000ull * DEGCAP];
__device__ unsigned g_ctr_stats;   // zero-init; last block resets -> replay-safe
__device__ unsigned g_ctr_cnt;

// ---------------- helpers ----------------
__device__ __forceinline__ float to_tf32(float x) {
    uint32_t r;
    asm("cvt.rn.tf32.f32 %0, %1;" : "=r"(r) : "f"(x));
    return __uint_as_float(r);
}
__device__ __forceinline__ void red_add_v4(float* a, float4 v) {
    asm volatile("red.global.add.v4.f32 [%0], {%1,%2,%3,%4};"
                 :: "l"(a), "f"(v.x), "f"(v.y), "f"(v.z), "f"(v.w) : "memory");
}
__device__ __forceinline__ void mma_tf32(float* c, const uint32_t* a,
                                         uint32_t b0, uint32_t b1) {
    asm volatile(
        "mma.sync.aligned.m16n8k8.row.col.f32.tf32.tf32.f32 "
        "{%0,%1,%2,%3}, {%4,%5,%6,%7}, {%8,%9}, {%0,%1,%2,%3};"
        : "+f"(c[0]), "+f"(c[1]), "+f"(c[2]), "+f"(c[3])
        : "r"(a[0]), "r"(a[1]), "r"(a[2]), "r"(a[3]), "r"(b0), "r"(b1));
}

// ---------------- setup kernels ----------------
// one pass zeroing: deg (25000 float4), out (out4 float4), cnt (128 float4)
__global__ void k_zeroall(float* __restrict__ degf, float* __restrict__ out,
                          int out4, float* __restrict__ cnt) {
    int t = blockIdx.x * blockDim.x + threadIdx.x;
    if (t < 25000) {
        reinterpret_cast<float4*>(degf)[t] = make_float4(0.f, 0.f, 0.f, 0.f);
    } else if (t < 25000 + out4) {
        reinterpret_cast<float4*>(out)[t - 25000] = make_float4(0.f, 0.f, 0.f, 0.f);
    } else if (t < 25000 + out4 + 128) {
        reinterpret_cast<float4*>(cnt)[t - 25000 - out4] = make_float4(0.f, 0.f, 0.f, 0.f);
    }
}

// both relations in one grid
__global__ void k_build2(const int* __restrict__ eu2i, const int* __restrict__ ei2u,
                         int* __restrict__ deg, int* __restrict__ csr) {
    int t = blockIdx.x * blockDim.x + threadIdx.x;
    if (t >= 2 * EC) return;
    const int* edge;
    int* dp;
    int* cp;
    int e;
    if (t < EC) { edge = eu2i; dp = deg; cp = csr; e = t; }
    else {
        edge = ei2u; dp = deg + 50000; cp = csr + (int)0; e = t - EC;
        cp = csr; cp += 50000ull * DEGCAP;
    }
    int src = edge[e];
    int dst = edge[EC + e];
    int pos = atomicAdd(&dp[dst], 1);
    if (pos < DEGCAP) cp[(size_t)dst * DEGCAP + pos] = src;
}

// smem-histogram count + fused inverse-count (last block)
__global__ void __launch_bounds__(1024) k_count(
    const int* __restrict__ bu, const int* __restrict__ bi,
    float* __restrict__ cnt, float* __restrict__ inv) {
    __shared__ int h[GC];
    for (int i = threadIdx.x; i < GC; i += 1024) h[i] = 0;
    __syncthreads();
    for (int t = blockIdx.x * 1024 + threadIdx.x; t < NU + NI;
         t += gridDim.x * 1024) {
        int b = (t < NU) ? bu[t] : bi[t - NU];
        atomicAdd(&h[b], 1);
    }
    __syncthreads();
    for (int i = threadIdx.x; i < GC; i += 1024)
        if (h[i]) atomicAdd(&cnt[i], (float)h[i]);
    __threadfence();
    __shared__ bool last;
    if (threadIdx.x == 0)
        last = (atomicAdd(&g_ctr_cnt, 1u) == gridDim.x - 1);
    __syncthreads();
    if (last) {
        if (threadIdx.x < GC)
            inv[threadIdx.x] = 1.0f / fmaxf(cnt[threadIdx.x], 1.0f);
        if (threadIdx.x == 0) g_ctr_cnt = 0;
    }
}

// merged gather (both relations); block 0 zeroes this layer's BN stats
__global__ void k_gather(const float* __restrict__ xu, const float* __restrict__ xi,
                         float* __restrict__ aggU, float* __restrict__ aggI,
                         float* __restrict__ stats) {
    if (blockIdx.x == 0 && threadIdx.x < 128) {
#pragma unroll
        for (int i = 0; i < 4; i++) stats[threadIdx.x + i * 128] = 0.f;
    }
    int t = blockIdx.x * blockDim.x + threadIdx.x;
    int gn = t >> 5, lane = t & 31;
    if (gn >= 100000) return;
    const float* x;
    float* dst;
    const int* dp;
    const int* lst;
    int node;
    if (gn < 50000) {
        node = gn; x = xu; dst = aggI; dp = g_deg;
        lst = g_csr + (size_t)node * DEGCAP;
    } else {
        node = gn - 50000; x = xi; dst = aggU; dp = g_deg + 50000;
        lst = g_csr + 50000ull * DEGCAP + (size_t)node * DEGCAP;
    }
    int d = min(dp[node], DEGCAP);
    float ax = 0.f, ay = 0.f, az = 0.f, aw = 0.f;
    int j = 0;
    for (; j + 4 <= d; j += 4) {
        int s0 = lst[j], s1 = lst[j + 1], s2 = lst[j + 2], s3 = lst[j + 3];
        float4 v0 = *reinterpret_cast<const float4*>(&x[(size_t)s0 * FH + lane * 4]);
        float4 v1 = *reinterpret_cast<const float4*>(&x[(size_t)s1 * FH + lane * 4]);
        float4 v2 = *reinterpret_cast<const float4*>(&x[(size_t)s2 * FH + lane * 4]);
        float4 v3 = *reinterpret_cast<const float4*>(&x[(size_t)s3 * FH + lane * 4]);
        ax += v0.x + v1.x + v2.x + v3.x;
        ay += v0.y + v1.y + v2.y + v3.y;
        az += v0.z + v1.z + v2.z + v3.z;
        aw += v0.w + v1.w + v2.w + v3.w;
    }
    for (; j < d; j++) {
        int s = lst[j];
        float4 v = *reinterpret_cast<const float4*>(&x[(size_t)s * FH + lane * 4]);
        ax += v.x; ay += v.y; az += v.z; aw += v.w;
    }
    *reinterpret_cast<float4*>(&dst[(size_t)node * FH + lane * 4]) =
        make_float4(ax, ay, az, aw);
}

// ---------------- mma.sync tf32 GEMM with fused BN-stats epilogue ----------------
// out[n,h] = sum_f A0[n,f]*Wa[h,f] + sum_f A1[n,f]*Wb[h,f] + bias[h]
// Epilogue: per-column relu sum/sumsq reduced in smem -> global stats atomics;
// last block computes BN scale/shift (replaces k_stats + k_bnparams).
__global__ void __launch_bounds__(256) k_gemm_mma(
    const float* __restrict__ aggI, const float* __restrict__ xI,
    const float* __restrict__ aggU, const float* __restrict__ xU,
    const float* __restrict__ WaI, const float* __restrict__ WbI,
    const float* __restrict__ WaU, const float* __restrict__ WbU,
    const float* __restrict__ bI, const float* __restrict__ bU,
    float* __restrict__ nI, float* __restrict__ nU,
    float* __restrict__ stats, float* __restrict__ bn,
    const float* __restrict__ gu, const float* __restrict__ bu_,
    const float* __restrict__ gi, const float* __restrict__ bi_) {
    __shared__ float sA[128 * 36];
    __shared__ float sW[128 * 36];

    int tid = threadIdx.x, wid = tid >> 5, lane = tid & 31;
    bool item = blockIdx.x < NT;
    int tile = item ? blockIdx.x : blockIdx.x - NT;
    const float* A0 = item ? aggI : aggU;
    const float* A1 = item ? xI : xU;
    const float* Wa = item ? WaI : WaU;
    const float* Wb = item ? WbI : WbU;
    const float* bias = item ? bI : bU;
    float* outp = item ? nI : nU;
    int row0 = tile * 128;

    int g = lane >> 2, q = lane & 3;
    int wm = wid & 3, wn = wid >> 2;
    int ar = tid >> 3, aj = tid & 7;

    float c[2][8][4];
#pragma unroll
    for (int mt = 0; mt < 2; mt++)
#pragma unroll
        for (int nt = 0; nt < 8; nt++)
#pragma unroll
            for (int e = 0; e < 4; e++) c[mt][nt][e] = 0.f;

    float4 pa[4], pw[4];

    // prologue: fetch chunk 0
    {
#pragma unroll
        for (int i = 0; i < 4; i++) {
            int r = ar + i * 32;
            pa[i] = (row0 + r < 50000)
                        ? *reinterpret_cast<const float4*>(
                              &A0[(size_t)(row0 + r) * FH + aj * 4])
                        : make_float4(0.f, 0.f, 0.f, 0.f);
            pw[i] = *reinterpret_cast<const float4*>(&Wa[r * FH + aj * 4]);
        }
    }
#pragma unroll
    for (int i = 0; i < 4; i++) {
        int r = ar + i * 32;
        float4 va = pa[i], vw = pw[i];
        va.x = to_tf32(va.x); va.y = to_tf32(va.y);
        va.z = to_tf32(va.z); va.w = to_tf32(va.w);
        vw.x = to_tf32(vw.x); vw.y = to_tf32(vw.y);
        vw.z = to_tf32(vw.z); vw.w = to_tf32(vw.w);
        *reinterpret_cast<float4*>(&sA[r * 36 + aj * 4]) = va;
        *reinterpret_cast<float4*>(&sW[r * 36 + aj * 4]) = vw;
    }
    __syncthreads();

#pragma unroll 1
    for (int ch = 0; ch < 8; ch++) {
        if (ch < 7) {
            int cn = ch + 1;
            const float* Ap = (cn < 4) ? A0 : A1;
            const float* Wp = (cn < 4) ? Wa : Wb;
            int f0 = (cn & 3) * 32;
#pragma unroll
            for (int i = 0; i < 4; i++) {
                int r = ar + i * 32;
                pa[i] = (row0 + r < 50000)
                            ? *reinterpret_cast<const float4*>(
                                  &Ap[(size_t)(row0 + r) * FH + f0 + aj * 4])
                            : make_float4(0.f, 0.f, 0.f, 0.f);
                pw[i] = *reinterpret_cast<const float4*>(&Wp[r * FH + f0 + aj * 4]);
            }
        }

#pragma unroll
        for (int s = 0; s < 4; s++) {
            int k0 = s * 8;
            uint32_t a[2][4];
#pragma unroll
            for (int mt = 0; mt < 2; mt++) {
                int m0 = wm * 32 + mt * 16;
                a[mt][0] = __float_as_uint(sA[(m0 + g) * 36 + k0 + q]);
                a[mt][1] = __float_as_uint(sA[(m0 + g + 8) * 36 + k0 + q]);
                a[mt][2] = __float_as_uint(sA[(m0 + g) * 36 + k0 + q + 4]);
                a[mt][3] = __float_as_uint(sA[(m0 + g + 8) * 36 + k0 + q + 4]);
            }
#pragma unroll
            for (int nt = 0; nt < 8; nt++) {
                int n0 = wn * 64 + nt * 8;
                uint32_t b0 = __float_as_uint(sW[(n0 + g) * 36 + k0 + q]);
                uint32_t b1 = __float_as_uint(sW[(n0 + g) * 36 + k0 + q + 4]);
                mma_tf32(c[0][nt], a[0], b0, b1);
                mma_tf32(c[1][nt], a[1], b0, b1);
            }
        }
        __syncthreads();

        if (ch < 7) {
#pragma unroll
            for (int i = 0; i < 4; i++) {
                int r = ar + i * 32;
                float4 va = pa[i], vw = pw[i];
                va.x = to_tf32(va.x); va.y = to_tf32(va.y);
                va.z = to_tf32(va.z); va.w = to_tf32(va.w);
                vw.x = to_tf32(vw.x); vw.y = to_tf32(vw.y);
                vw.z = to_tf32(vw.z); vw.w = to_tf32(vw.w);
                *reinterpret_cast<float4*>(&sA[r * 36 + aj * 4]) = va;
                *reinterpret_cast<float4*>(&sW[r * 36 + aj * 4]) = vw;
            }
            __syncthreads();
        }
    }

    // ---- epilogue: write output + per-column relu stats in smem ----
    float* scol = sA;                 // [0..127] sum, [128..255] sumsq
    scol[tid] = 0.f;                  // blockDim == 256
    __syncthreads();

#pragma unroll
    for (int nt = 0; nt < 8; nt++) {
        int n0 = wn * 64 + nt * 8 + 2 * q;
        float2 bb = *reinterpret_cast<const float2*>(&bias[n0]);
        float s0 = 0.f, q0 = 0.f, s1 = 0.f, q1 = 0.f;
#pragma unroll
        for (int mt = 0; mt < 2; mt++) {
            int r = row0 + wm * 32 + mt * 16 + g;
            if (r < 50000) {
                float ox = c[mt][nt][0] + bb.x;
                float oy = c[mt][nt][1] + bb.y;
                *reinterpret_cast<float2*>(&outp[(size_t)r * FH + n0]) =
                    make_float2(ox, oy);
                float vx = fmaxf(ox, 0.f), vy = fmaxf(oy, 0.f);
                s0 += vx; q0 += vx * vx; s1 += vy; q1 += vy * vy;
            }
            if (r + 8 < 50000) {
                float ox = c[mt][nt][2] + bb.x;
                float oy = c[mt][nt][3] + bb.y;
                *reinterpret_cast<float2*>(&outp[(size_t)(r + 8) * FH + n0]) =
                    make_float2(ox, oy);
                float vx = fmaxf(ox, 0.f), vy = fmaxf(oy, 0.f);
                s0 += vx; q0 += vx * vx; s1 += vy; q1 += vy * vy;
            }
        }
        atomicAdd(&scol[n0], s0);
        atomicAdd(&scol[128 + n0], q0);
        atomicAdd(&scol[n0 + 1], s1);
        atomicAdd(&scol[128 + n0 + 1], q1);
    }
    __syncthreads();

    float* sg = item ? stats + 256 : stats;   // [h]=sum, [h+128]=sumsq
    atomicAdd(&sg[tid], scol[tid]);

    __threadfence();
    __shared__ bool lastb;
    if (tid == 0)
        lastb = (atomicAdd(&g_ctr_stats, 1u) == 2 * NT - 1);
    __syncthreads();
    if (lastb) {
#pragma unroll
        for (int rep = 0; rep < 2; rep++) {
            int t2 = tid + rep * 256;
            if (t2 < 256) {
                int hh = t2 & 127;
                const float* ss = (t2 < 128) ? stats : stats + 256;
                const float* gg = (t2 < 128) ? gu : gi;
                const float* be = (t2 < 128) ? bu_ : bi_;
                float* o = (t2 < 128) ? bn : bn + 256;
                float invn = 1.0f / 50000.0f;
                float m = ss[hh] * invn;
                float var = ss[hh + 128] * invn - m * m;
                float sc = gg[hh] * rsqrtf(var + BN_EPS);
                o[hh] = sc;
                o[hh + 128] = be[hh] - m * sc;
            }
        }
        if (tid == 0) g_ctr_stats = 0;
    }
}

// ---------------- apply / logits ----------------
__global__ void k_apply(const float* __restrict__ nu_, const float* __restrict__ ni_,
                        const float* __restrict__ bn, const int* __restrict__ bu,
                        const int* __restrict__ bi, const float* __restrict__ inv,
                        float* __restrict__ XU, float* __restrict__ XI,
                        float* __restrict__ pooled) {
    int t = blockIdx.x * blockDim.x + threadIdx.x;
    if (t >= (NU + NI) * 32) return;
    int gn = t >> 5, lane = t & 31;
    const float* v;
    const float* sc;
    const int* bt;
    float* xo;
    int r;
    if (gn < NU) { v = nu_; sc = bn; bt = bu; xo = XU; r = gn; }
    else { v = ni_; sc = bn + 256; bt = bi; xo = XI; r = gn - NU; }
    int g = bt[r];
    float ic = inv[g];
    float4 x = *reinterpret_cast<const float4*>(&v[(size_t)r * FH + lane * 4]);
    float4 s4 = *reinterpret_cast<const float4*>(&sc[lane * 4]);
    float4 h4 = *reinterpret_cast<const float4*>(&sc[128 + lane * 4]);
    float4 y;
    y.x = fmaxf(x.x, 0.f) * s4.x + h4.x;
    y.y = fmaxf(x.y, 0.f) * s4.y + h4.y;
    y.z = fmaxf(x.z, 0.f) * s4.z + h4.z;
    y.w = fmaxf(x.w, 0.f) * s4.w + h4.w;
    *reinterpret_cast<float4*>(&xo[(size_t)r * FH + lane * 4]) = y;
    red_add_v4(&pooled[(size_t)g * FH + lane * 4],
               make_float4(y.x * ic, y.y * ic, y.z * ic, y.w * ic));
}

__global__ void k_logits(const float* __restrict__ feats, const float* __restrict__ fcW,
                         const float* __restrict__ fcb, float* __restrict__ out) {
    int lg = blockIdx.x;
    int l = lg / GC;
    __shared__ float sf[FH];
    sf[threadIdx.x] = feats[(size_t)lg * FH + threadIdx.x];
    __syncthreads();
    int c = threadIdx.x;
    if (c < CC) {
        const float* w = &fcW[(size_t)(l * CC + c) * FH];
        float a = fcb[l * CC + c];
#pragma unroll 8
        for (int h = 0; h < FH; h++) a += sf[h] * w[h];
        out[(size_t)lg * CC + c] = a;
    }
}

// ---------------------------------------------------------------------------
extern "C" void kernel_launch(void* const* d_in, const int* in_sizes, int n_in,
                              void* d_out, int out_size) {
    const float* x_user    = (const float*)d_in[0];
    const float* x_item    = (const float*)d_in[1];
    const int*   e_u2i     = (const int*)d_in[2];
    const int*   e_i2u     = (const int*)d_in[3];
    const int*   b_user    = (const int*)d_in[4];
    const int*   b_item    = (const int*)d_in[5];
    const float* Wrel_u2i  = (const float*)d_in[6];
    const float* Wroot_u2i = (const float*)d_in[7];
    const float* bias_u2i  = (const float*)d_in[8];
    const float* Wrel_i2u  = (const float*)d_in[9];
    const float* Wroot_i2u = (const float*)d_in[10];
    const float* bias_i2u  = (const float*)d_in[11];
    const float* bng_u     = (const float*)d_in[12];
    const float* bnb_u     = (const float*)d_in[13];
    const float* bng_i     = (const float*)d_in[14];
    const float* bnb_i     = (const float*)d_in[15];
    const float* fcW       = (const float*)d_in[16];
    const float* fcb       = (const float*)d_in[17];
    float* out = (float*)d_out;

    float* buf = nullptr;
    cudaGetSymbolAddress((void**)&buf, g_buf);
    int* deg = nullptr;
    cudaGetSymbolAddress((void**)&deg, g_deg);
    int* csr = nullptr;
    cudaGetSymbolAddress((void**)&csr, g_csr);

    float* XU    = buf + OFF_XU;
    float* XI    = buf + OFF_XI;
    float* agg_u = buf + OFF_AGU;
    float* agg_i = buf + OFF_AGI;
    float* new_u = buf + OFF_NWU;
    float* new_i = buf + OFF_NWI;
    float* cnt   = buf + OFF_CNT;
    float* inv   = buf + OFF_INV;
    float* stats = buf + OFF_STATS;
    float* bn    = buf + OFF_BN;

    const int OUT_ELEMS = LC * GC * CC + LC * GC * FH;   // 221184
    const int OUT4 = OUT_ELEMS / 4;                      // 55296
    float* feats = out + LC * GC * CC;

    const int ZTOT = 25000 + OUT4 + 128;

    // 0: zero deg + out + cnt
    k_zeroall<<<(ZTOT + 255) / 256, 256>>>((float*)deg, out, OUT4, cnt);
    // 1: build both CSR bucket sets
    k_build2<<<(2 * EC + 255) / 256, 256>>>(e_u2i, e_i2u, deg, csr);
    // 2: layer-0 gather
    k_gather<<<(100000 * 32 + 255) / 256, 256>>>(x_user, x_item, agg_u, agg_i, stats);
    // 3: layer-0 GEMM (ncu captures this)
    {
        size_t wo = 0;
        k_gemm_mma<<<2 * NT, 256>>>(agg_i, x_item, agg_u, x_user,
                                    Wrel_u2i + wo, Wroot_u2i + wo,
                                    Wrel_i2u + wo, Wroot_i2u + wo,
                                    bias_u2i, bias_i2u, new_i, new_u,
                                    stats, bn, bng_u, bnb_u, bng_i, bnb_i);
    }
    // 4: group counts + inverse (needed only by apply)
    k_count<<<64, 1024>>>(b_user, b_item, cnt, inv);
    // 5: layer-0 apply
    k_apply<<<((NU + NI) * 32 + 255) / 256, 256>>>(new_u, new_i, bn, b_user,
                                                   b_item, inv, XU, XI, feats);

    for (int l = 1; l < LC; l++) {
        k_gather<<<(100000 * 32 + 255) / 256, 256>>>(XU, XI, agg_u, agg_i, stats);
        size_t wo = (size_t)l * FH * FH;
        k_gemm_mma<<<2 * NT, 256>>>(agg_i, XI, agg_u, XU,
                                    Wrel_u2i + wo, Wroot_u2i + wo,
                                    Wrel_i2u + wo, Wroot_i2u + wo,
                                    bias_u2i + l * FH, bias_i2u + l * FH,
                                    new_i, new_u,
                                    stats, bn, bng_u, bnb_u, bng_i, bnb_i);
        float* fl = feats + (size_t)l * GC * FH;
        k_apply<<<((NU + NI) * 32 + 255) / 256, 256>>>(new_u, new_i, bn, b_user,
                                                       b_item, inv, XU, XI, fl);
    }

    k_logits<<<LC * GC, FH>>>(feats, fcW, fcb, out);
}

// round 10
// speedup vs baseline: 1.2099x; 1.2099x over previous
#include <cuda_runtime.h>
#include <cstdint>

#define NU 50000
#define NI 50000
#define FH 128
#define EC 800000
#define GC 512
#define CC 16
#define LC 3
#define BN_EPS 1e-5f
#define DEGCAP 96
#define NT 391

#define NODEF (50000ull * 128ull)
#define OFF_XU 0ull
#define OFF_XI (1ull * NODEF)
#define OFF_AGU (2ull * NODEF)
#define OFF_AGI (3ull * NODEF)
#define OFF_NWU (4ull * NODEF)
#define OFF_NWI (5ull * NODEF)
#define OFF_CNT (6ull * NODEF)
#define OFF_INV (OFF_CNT + 512ull)
#define OFF_STATS (OFF_INV + 512ull)
#define OFF_BN (OFF_STATS + 512ull)
#define BUF_TOTAL (OFF_BN + 512ull)

__device__ float g_buf[BUF_TOTAL];
__device__ int g_deg[2 * 50000];
__device__ int g_csr[2ull * 50000ull * DEGCAP];
__device__ unsigned g_ctr_stats;
__device__ unsigned g_ctr_cnt;

// ---------------- helpers ----------------
__device__ __forceinline__ uint32_t smem_u32(const void* p) {
    uint32_t a;
    asm("{ .reg .u64 t; cvta.to.shared.u64 t, %1; cvt.u32.u64 %0, t; }" : "=r"(a) : "l"(p));
    return a;
}
__device__ __forceinline__ float to_tf32(float x) {
    uint32_t r;
    asm("cvt.rn.tf32.f32 %0, %1;" : "=r"(r) : "f"(x));
    return __uint_as_float(r);
}
__device__ __forceinline__ void red_add_v4(float* a, float4 v) {
    asm volatile("red.global.add.v4.f32 [%0], {%1,%2,%3,%4};"
                 :: "l"(a), "f"(v.x), "f"(v.y), "f"(v.z), "f"(v.w) : "memory");
}
__device__ __forceinline__ void mma_tf32(float* c, const uint32_t* a,
                                         uint32_t b0, uint32_t b1) {
    asm volatile(
        "mma.sync.aligned.m16n8k8.row.col.f32.tf32.tf32.f32 "
        "{%0,%1,%2,%3}, {%4,%5,%6,%7}, {%8,%9}, {%0,%1,%2,%3};"
        : "+f"(c[0]), "+f"(c[1]), "+f"(c[2]), "+f"(c[3])
        : "r"(a[0]), "r"(a[1]), "r"(a[2]), "r"(a[3]), "r"(b0), "r"(b1));
}
__device__ __forceinline__ void cp16(uint32_t s, const float* g, int sz) {
    asm volatile("cp.async.ca.shared.global [%0], [%1], 16, %2;"
                 :: "r"(s), "l"(g), "r"(sz) : "memory");
}
#define CP_COMMIT() asm volatile("cp.async.commit_group;" ::: "memory")

// ---------------- setup kernels ----------------
// zero deg/out/cnt + pre-round inputs into XU/XI (tf32)
__global__ void k_zeroall(float* __restrict__ degf, float* __restrict__ out,
                          int out4, float* __restrict__ cnt,
                          const float* __restrict__ xu, const float* __restrict__ xi,
                          float* __restrict__ XU, float* __restrict__ XI) {
    int t = blockIdx.x * blockDim.x + threadIdx.x;
    if (t < 25000) {
        reinterpret_cast<float4*>(degf)[t] = make_float4(0.f, 0.f, 0.f, 0.f);
    } else if (t < 25000 + out4) {
        reinterpret_cast<float4*>(out)[t - 25000] = make_float4(0.f, 0.f, 0.f, 0.f);
    } else if (t < 25000 + out4 + 128) {
        reinterpret_cast<float4*>(cnt)[t - 25000 - out4] = make_float4(0.f, 0.f, 0.f, 0.f);
    } else {
        int q = t - (25000 + out4 + 128);
        if (q < 3200000) {
            const float* s;
            float* d;
            if (q < 1600000) { s = xu; d = XU; } else { s = xi; d = XI; q -= 1600000; }
            float4 v = reinterpret_cast<const float4*>(s)[q];
            reinterpret_cast<float4*>(d)[q] =
                make_float4(to_tf32(v.x), to_tf32(v.y), to_tf32(v.z), to_tf32(v.w));
        }
    }
}

// both relations in one grid
__global__ void k_build2(const int* __restrict__ eu2i, const int* __restrict__ ei2u,
                         int* __restrict__ deg, int* __restrict__ csr) {
    int t = blockIdx.x * blockDim.x + threadIdx.x;
    if (t >= 2 * EC) return;
    const int* edge = (t < EC) ? eu2i : ei2u;
    int e = (t < EC) ? t : t - EC;
    int* dp = (t < EC) ? deg : deg + 50000;
    int* cp = (t < EC) ? csr : csr + 50000ull * DEGCAP;
    int src = edge[e];
    int dst = edge[EC + e];
    int pos = atomicAdd(&dp[dst], 1);
    if (pos < DEGCAP) cp[(size_t)dst * DEGCAP + pos] = src;
}

// smem-histogram count + fused inverse-count (last block)
__global__ void __launch_bounds__(1024) k_count(
    const int* __restrict__ bu, const int* __restrict__ bi,
    float* __restrict__ cnt, float* __restrict__ inv) {
    __shared__ int h[GC];
    for (int i = threadIdx.x; i < GC; i += 1024) h[i] = 0;
    __syncthreads();
    for (int t = blockIdx.x * 1024 + threadIdx.x; t < NU + NI;
         t += gridDim.x * 1024) {
        int b = (t < NU) ? bu[t] : bi[t - NU];
        atomicAdd(&h[b], 1);
    }
    __syncthreads();
    for (int i = threadIdx.x; i < GC; i += 1024)
        if (h[i]) atomicAdd(&cnt[i], (float)h[i]);
    __threadfence();
    __shared__ bool last;
    if (threadIdx.x == 0)
        last = (atomicAdd(&g_ctr_cnt, 1u) == gridDim.x - 1);
    __syncthreads();
    if (last) {
        if (threadIdx.x < GC)
            inv[threadIdx.x] = 1.0f / fmaxf(cnt[threadIdx.x], 1.0f);
        if (threadIdx.x == 0) g_ctr_cnt = 0;
    }
}

// merged gather; writes tf32-rounded agg; block 0 zeroes this layer's stats
__global__ void k_gather(const float* __restrict__ xu, const float* __restrict__ xi,
                         float* __restrict__ aggU, float* __restrict__ aggI,
                         float* __restrict__ stats) {
    if (blockIdx.x == 0 && threadIdx.x < 128) {
#pragma unroll
        for (int i = 0; i < 4; i++) stats[threadIdx.x + i * 128] = 0.f;
    }
    int t = blockIdx.x * blockDim.x + threadIdx.x;
    int gn = t >> 5, lane = t & 31;
    if (gn >= 100000) return;
    const float* x;
    float* dst;
    const int* dp;
    const int* lst;
    int node;
    if (gn < 50000) {
        node = gn; x = xu; dst = aggI; dp = g_deg;
        lst = g_csr + (size_t)node * DEGCAP;
    } else {
        node = gn - 50000; x = xi; dst = aggU; dp = g_deg + 50000;
        lst = g_csr + 50000ull * DEGCAP + (size_t)node * DEGCAP;
    }
    int d = min(dp[node], DEGCAP);
    float ax = 0.f, ay = 0.f, az = 0.f, aw = 0.f;
    int j = 0;
    for (; j + 4 <= d; j += 4) {
        int s0 = lst[j], s1 = lst[j + 1], s2 = lst[j + 2], s3 = lst[j + 3];
        float4 v0 = *reinterpret_cast<const float4*>(&x[(size_t)s0 * FH + lane * 4]);
        float4 v1 = *reinterpret_cast<const float4*>(&x[(size_t)s1 * FH + lane * 4]);
        float4 v2 = *reinterpret_cast<const float4*>(&x[(size_t)s2 * FH + lane * 4]);
        float4 v3 = *reinterpret_cast<const float4*>(&x[(size_t)s3 * FH + lane * 4]);
        ax += v0.x + v1.x + v2.x + v3.x;
        ay += v0.y + v1.y + v2.y + v3.y;
        az += v0.z + v1.z + v2.z + v3.z;
        aw += v0.w + v1.w + v2.w + v3.w;
    }
    for (; j < d; j++) {
        int s = lst[j];
        float4 v = *reinterpret_cast<const float4*>(&x[(size_t)s * FH + lane * 4]);
        ax += v.x; ay += v.y; az += v.z; aw += v.w;
    }
    *reinterpret_cast<float4*>(&dst[(size_t)node * FH + lane * 4]) =
        make_float4(to_tf32(ax), to_tf32(ay), to_tf32(az), to_tf32(aw));
}

// ---------------- mma.sync tf32 GEMM, cp.async double-buffered ----------------
// Operands are pre-rounded to tf32 by producers; staging is pure async copy.
#define CHF 4608                       // floats per 128x36 buffer
#define GSMEM (4 * CHF * 4)            // 73728 bytes

__global__ void __launch_bounds__(256, 2) k_gemm_mma(
    const float* __restrict__ aggI, const float* __restrict__ xI,
    const float* __restrict__ aggU, const float* __restrict__ xU,
    const float* __restrict__ WaI, const float* __restrict__ WbI,
    const float* __restrict__ WaU, const float* __restrict__ WbU,
    const float* __restrict__ bI, const float* __restrict__ bU,
    float* __restrict__ nI, float* __restrict__ nU) {
    extern __shared__ float sm[];
    int tid = threadIdx.x, wid = tid >> 5, lane = tid & 31;
    bool item = blockIdx.x < NT;
    int tile = item ? blockIdx.x : blockIdx.x - NT;
    const float* A0 = item ? aggI : aggU;
    const float* A1 = item ? xI : xU;
    const float* Wa = item ? WaI : WaU;
    const float* Wb = item ? WbI : WbU;
    const float* bias = item ? bI : bU;
    float* outp = item ? nI : nU;
    int row0 = tile * 128;

    int g = lane >> 2, q = lane & 3;
    int wm = wid & 3, wn = wid >> 2;

    uint32_t sA_u = smem_u32(sm);
    uint32_t sW_u = sA_u + 2 * CHF * 4;

    float c[2][8][4];
#pragma unroll
    for (int mt = 0; mt < 2; mt++)
#pragma unroll
        for (int nt = 0; nt < 8; nt++)
#pragma unroll
            for (int e = 0; e < 4; e++) c[mt][nt][e] = 0.f;

    // stage chunk ch into buffer b: A 128x32 + W 128x32, 16B lines
    auto stage = [&](int ch, int b) {
        const float* Ap = (ch < 4) ? A0 : A1;
        const float* Wp = (ch < 4) ? Wa : Wb;
        int f0 = (ch & 3) * 32;
        uint32_t ao = sA_u + b * CHF * 4;
        uint32_t wo = sW_u + b * CHF * 4;
#pragma unroll
        for (int i = 0; i < 4; i++) {
            int idx = i * 256 + tid;       // 0..1023
            int r = idx >> 3, j = idx & 7;
            int gr = row0 + r;
            int sz = (gr < 50000) ? 16 : 0;
            int grc = min(gr, 49999);
            cp16(ao + (r * 36 + j * 4) * 4, Ap + (size_t)grc * FH + f0 + j * 4, sz);
            cp16(wo + (r * 36 + j * 4) * 4, Wp + r * FH + f0 + j * 4, 16);
        }
    };

    stage(0, 0); CP_COMMIT();
    stage(1, 1); CP_COMMIT();

#pragma unroll 1
    for (int ch = 0; ch < 8; ch++) {
        if (ch < 7) asm volatile("cp.async.wait_group 1;" ::: "memory");
        else        asm volatile("cp.async.wait_group 0;" ::: "memory");
        __syncthreads();

        const float* sA = sm + (ch & 1) * CHF;
        const float* sW = sm + 2 * CHF + (ch & 1) * CHF;

#pragma unroll
        for (int s = 0; s < 4; s++) {
            int k0 = s * 8;
            uint32_t a[2][4];
#pragma unroll
            for (int mt = 0; mt < 2; mt++) {
                int m0 = wm * 32 + mt * 16;
                a[mt][0] = __float_as_uint(sA[(m0 + g) * 36 + k0 + q]);
                a[mt][1] = __float_as_uint(sA[(m0 + g + 8) * 36 + k0 + q]);
                a[mt][2] = __float_as_uint(sA[(m0 + g) * 36 + k0 + q + 4]);
                a[mt][3] = __float_as_uint(sA[(m0 + g + 8) * 36 + k0 + q + 4]);
            }
#pragma unroll
            for (int nt = 0; nt < 8; nt++) {
                int n0 = wn * 64 + nt * 8;
                uint32_t b0 = __float_as_uint(sW[(n0 + g) * 36 + k0 + q]);
                uint32_t b1 = __float_as_uint(sW[(n0 + g) * 36 + k0 + q + 4]);
                mma_tf32(c[0][nt], a[0], b0, b1);
                mma_tf32(c[1][nt], a[1], b0, b1);
            }
        }
        __syncthreads();

        if (ch < 6) { stage(ch + 2, ch & 1); CP_COMMIT(); }
    }

    // epilogue: bias add + store
#pragma unroll
    for (int nt = 0; nt < 8; nt++) {
        int n0 = wn * 64 + nt * 8 + 2 * q;
        float2 bb = *reinterpret_cast<const float2*>(&bias[n0]);
#pragma unroll
        for (int mt = 0; mt < 2; mt++) {
            int r = row0 + wm * 32 + mt * 16 + g;
            if (r < 50000) {
                float2 o = make_float2(c[mt][nt][0] + bb.x, c[mt][nt][1] + bb.y);
                *reinterpret_cast<float2*>(&outp[(size_t)r * FH + n0]) = o;
            }
            if (r + 8 < 50000) {
                float2 o = make_float2(c[mt][nt][2] + bb.x, c[mt][nt][3] + bb.y);
                *reinterpret_cast<float2*>(&outp[(size_t)(r + 8) * FH + n0]) = o;
            }
        }
    }
}

// ---------------- BN stats with fused bnparams (last-block) ----------------
__global__ void k_stats(const float* __restrict__ nu_, const float* __restrict__ ni_,
                        float* __restrict__ stats, float* __restrict__ bn,
                        const float* __restrict__ gu, const float* __restrict__ bu_,
                        const float* __restrict__ gi, const float* __restrict__ bi_) {
    int b = blockIdx.x;
    const float* v;
    float* s;
    int r0;
    if (b < NT) { v = nu_; s = stats; r0 = b * 128; }
    else { v = ni_; s = stats + 256; r0 = (b - NT) * 128; }
    int h = threadIdx.x;
    int re = min(r0 + 128, 50000);
    float a = 0.f, qq = 0.f;
    for (int r = r0; r < re; r++) {
        float x = fmaxf(v[(size_t)r * FH + h], 0.f);
        a += x;
        qq += x * x;
    }
    atomicAdd(&s[h], a);
    atomicAdd(&s[h + 128], qq);

    __threadfence();
    __shared__ bool last;
    if (threadIdx.x == 0)
        last = (atomicAdd(&g_ctr_stats, 1u) == 2 * NT - 1);
    __syncthreads();
    if (last) {
#pragma unroll
        for (int rep = 0; rep < 2; rep++) {
            int t2 = threadIdx.x + rep * 128;
            int hh = t2 & 127;
            const float* ss = (t2 < 128) ? stats : stats + 256;
            const float* gg = (t2 < 128) ? gu : gi;
            const float* be = (t2 < 128) ? bu_ : bi_;
            float* o = (t2 < 128) ? bn : bn + 256;
            float invn = 1.0f / 50000.0f;
            float m = ss[hh] * invn;
            float var = ss[hh + 128] * invn - m * m;
            float sc = gg[hh] * rsqrtf(var + BN_EPS);
            o[hh] = sc;
            o[hh + 128] = be[hh] - m * sc;
        }
        if (threadIdx.x == 0) g_ctr_stats = 0;
    }
}

// apply relu+BN; write tf32-rounded next features; accumulate pooled (exact)
__global__ void k_apply(const float* __restrict__ nu_, const float* __restrict__ ni_,
                        const float* __restrict__ bn, const int* __restrict__ bu,
                        const int* __restrict__ bi, const float* __restrict__ inv,
                        float* __restrict__ XU, float* __restrict__ XI,
                        float* __restrict__ pooled) {
    int t = blockIdx.x * blockDim.x + threadIdx.x;
    if (t >= (NU + NI) * 32) return;
    int gn = t >> 5, lane = t & 31;
    const float* v;
    const float* sc;
    const int* bt;
    float* xo;
    int r;
    if (gn < NU) { v = nu_; sc = bn; bt = bu; xo = XU; r = gn; }
    else { v = ni_; sc = bn + 256; bt = bi; xo = XI; r = gn - NU; }
    int g = bt[r];
    float ic = inv[g];
    float4 x = *reinterpret_cast<const float4*>(&v[(size_t)r * FH + lane * 4]);
    float4 s4 = *reinterpret_cast<const float4*>(&sc[lane * 4]);
    float4 h4 = *reinterpret_cast<const float4*>(&sc[128 + lane * 4]);
    float4 y;
    y.x = fmaxf(x.x, 0.f) * s4.x + h4.x;
    y.y = fmaxf(x.y, 0.f) * s4.y + h4.y;
    y.z = fmaxf(x.z, 0.f) * s4.z + h4.z;
    y.w = fmaxf(x.w, 0.f) * s4.w + h4.w;
    *reinterpret_cast<float4*>(&xo[(size_t)r * FH + lane * 4]) =
        make_float4(to_tf32(y.x), to_tf32(y.y), to_tf32(y.z), to_tf32(y.w));
    red_add_v4(&pooled[(size_t)g * FH + lane * 4],
               make_float4(y.x * ic, y.y * ic, y.z * ic, y.w * ic));
}

__global__ void k_logits(const float* __restrict__ feats, const float* __restrict__ fcW,
                         const float* __restrict__ fcb, float* __restrict__ out) {
    int lg = blockIdx.x;
    int l = lg / GC;
    __shared__ float sf[FH];
    sf[threadIdx.x] = feats[(size_t)lg * FH + threadIdx.x];
    __syncthreads();
    int c = threadIdx.x;
    if (c < CC) {
        const float* w = &fcW[(size_t)(l * CC + c) * FH];
        float a = fcb[l * CC + c];
#pragma unroll 8
        for (int h = 0; h < FH; h++) a += sf[h] * w[h];
        out[(size_t)lg * CC + c] = a;
    }
}

// ---------------------------------------------------------------------------
extern "C" void kernel_launch(void* const* d_in, const int* in_sizes, int n_in,
                              void* d_out, int out_size) {
    const float* x_user    = (const float*)d_in[0];
    const float* x_item    = (const float*)d_in[1];
    const int*   e_u2i     = (const int*)d_in[2];
    const int*   e_i2u     = (const int*)d_in[3];
    const int*   b_user    = (const int*)d_in[4];
    const int*   b_item    = (const int*)d_in[5];
    const float* Wrel_u2i  = (const float*)d_in[6];
    const float* Wroot_u2i = (const float*)d_in[7];
    const float* bias_u2i  = (const float*)d_in[8];
    const float* Wrel_i2u  = (const float*)d_in[9];
    const float* Wroot_i2u = (const float*)d_in[10];
    const float* bias_i2u  = (const float*)d_in[11];
    const float* bng_u     = (const float*)d_in[12];
    const float* bnb_u     = (const float*)d_in[13];
    const float* bng_i     = (const float*)d_in[14];
    const float* bnb_i     = (const float*)d_in[15];
    const float* fcW       = (const float*)d_in[16];
    const float* fcb       = (const float*)d_in[17];
    float* out = (float*)d_out;

    float* buf = nullptr;
    cudaGetSymbolAddress((void**)&buf, g_buf);
    int* deg = nullptr;
    cudaGetSymbolAddress((void**)&deg, g_deg);
    int* csr = nullptr;
    cudaGetSymbolAddress((void**)&csr, g_csr);

    cudaFuncSetAttribute(k_gemm_mma, cudaFuncAttributeMaxDynamicSharedMemorySize, GSMEM);

    float* XU    = buf + OFF_XU;
    float* XI    = buf + OFF_XI;
    float* agg_u = buf + OFF_AGU;
    float* agg_i = buf + OFF_AGI;
    float* new_u = buf + OFF_NWU;
    float* new_i = buf + OFF_NWI;
    float* cnt   = buf + OFF_CNT;
    float* inv   = buf + OFF_INV;
    float* stats = buf + OFF_STATS;
    float* bn    = buf + OFF_BN;

    const int OUT_ELEMS = LC * GC * CC + LC * GC * FH;   // 221184
    const int OUT4 = OUT_ELEMS / 4;                      // 55296
    float* feats = out + LC * GC * CC;

    const int ZTOT = 25000 + OUT4 + 128 + 3200000;

    // 0: zero deg/out/cnt + pre-round inputs into XU/XI
    k_zeroall<<<(ZTOT + 255) / 256, 256>>>((float*)deg, out, OUT4, cnt,
                                           x_user, x_item, XU, XI);
    // 1: build both CSR bucket sets
    k_build2<<<(2 * EC + 255) / 256, 256>>>(e_u2i, e_i2u, deg, csr);
    // 2: layer-0 gather (reads raw inputs, writes rounded agg, zeroes stats)
    k_gather<<<(100000 * 32 + 255) / 256, 256>>>(x_user, x_item, agg_u, agg_i, stats);
    // 3: layer-0 GEMM (ncu captures this launch)
    k_gemm_mma<<<2 * NT, 256, GSMEM>>>(agg_i, XI, agg_u, XU,
                                       Wrel_u2i, Wroot_u2i,
                                       Wrel_i2u, Wroot_i2u,
                                       bias_u2i, bias_i2u, new_i, new_u);
    // 4: group counts + inverse
    k_count<<<64, 1024>>>(b_user, b_item, cnt, inv);
    // 5: BN stats + params
    k_stats<<<2 * NT, 128>>>(new_u, new_i, stats, bn, bng_u, bnb_u, bng_i, bnb_i);
    // 6: layer-0 apply
    k_apply<<<((NU + NI) * 32 + 255) / 256, 256>>>(new_u, new_i, bn, b_user,
                                                   b_item, inv, XU, XI, feats);

    for (int l = 1; l < LC; l++) {
        k_gather<<<(100000 * 32 + 255) / 256, 256>>>(XU, XI, agg_u, agg_i, stats);
        size_t wo = (size_t)l * FH * FH;
        k_gemm_mma<<<2 * NT, 256, GSMEM>>>(agg_i, XI, agg_u, XU,
                                           Wrel_u2i + wo, Wroot_u2i + wo,
                                           Wrel_i2u + wo, Wroot_i2u + wo,
                                           bias_u2i + l * FH, bias_i2u + l * FH,
                                           new_i, new_u);
        k_stats<<<2 * NT, 128>>>(new_u, new_i, stats, bn, bng_u, bnb_u, bng_i, bnb_i);
        float* fl = feats + (size_t)l * GC * FH;
        k_apply<<<((NU + NI) * 32 + 255) / 256, 256>>>(new_u, new_i, bn, b_user,
                                                       b_item, inv, XU, XI, fl);
    }

    k_logits<<<LC * GC, FH>>>(feats, fcW, fcb, out);
}